// round 7
// baseline (speedup 1.0000x reference)
#include <cuda_runtime.h>
#include <math.h>

#define Hdim   768
#define FFdim  3072
#define NLAY   12
#define NHEADS 12
#define DHEAD  64
#define BATCH  4
#define SEQ    512
#define MTOK   (BATCH*SEQ)   // 2048
#define NEnt   12
#define NRel   13

// ---------------- scratch (static device globals; no allocation) -------------
__device__ float g_x[MTOK*Hdim];
__device__ float g_xr[MTOK*Hdim];      // tf32-rounded copy of x (GEMM A side)
__device__ float g_q[MTOK*Hdim];
__device__ float g_k[MTOK*Hdim];
__device__ float g_v[MTOK*Hdim];
__device__ float g_ctx[MTOK*Hdim];
__device__ float g_ffn[MTOK*FFdim];
__device__ float g_scores[(size_t)BATCH*NHEADS*SEQ*SEQ];
__device__ float g_pi[MTOK*NRel];
__device__ float g_pj[MTOK*NRel];
__device__ float g_abias[BATCH*SEQ];

// ---------------- tf32 helpers ------------------------------------------------
__device__ __forceinline__ unsigned f2tf(float f) {
    unsigned u;
    asm("cvt.rna.tf32.f32 %0, %1;" : "=r"(u) : "f"(f));
    return u;
}
__device__ __forceinline__ float roundtf(float f) { return __uint_as_float(f2tf(f)); }
__device__ __forceinline__ void mma8(float* c, unsigned a0, unsigned a1,
                                     unsigned a2, unsigned a3,
                                     unsigned b0, unsigned b1) {
    asm volatile(
        "mma.sync.aligned.m16n8k8.row.col.f32.tf32.tf32.f32 "
        "{%0,%1,%2,%3},{%4,%5,%6,%7},{%8,%9},{%0,%1,%2,%3};"
        : "+f"(c[0]), "+f"(c[1]), "+f"(c[2]), "+f"(c[3])
        : "r"(a0), "r"(a1), "r"(a2), "r"(a3), "r"(b0), "r"(b1));
}
#define CPA16(dst, src) \
    asm volatile("cp.async.ca.shared.global [%0], [%1], 16;" :: "r"(dst), "l"(src))
__device__ __forceinline__ void cp_commit() { asm volatile("cp.async.commit_group;"); }

// ---------------- embedding + LayerNorm ---------------------------------------
__global__ __launch_bounds__(256) void embed_ln_kernel(
    const int* __restrict__ ids, const float* __restrict__ ew,
    const float* __restrict__ ep, const float* __restrict__ et,
    const float* __restrict__ g, const float* __restrict__ b)
{
    int t = blockIdx.x;
    int s = t & (SEQ - 1);
    int id = ids[t];
    int tid = threadIdx.x;
    float vals[3];
    float sum = 0.f;
#pragma unroll
    for (int i = 0; i < 3; i++) {
        int c = tid + i * 256;
        vals[i] = ew[(size_t)id * Hdim + c] + ep[(size_t)s * Hdim + c] + et[c];
        sum += vals[i];
    }
    __shared__ float red[256];
    red[tid] = sum; __syncthreads();
    for (int o = 128; o; o >>= 1) { if (tid < o) red[tid] += red[tid + o]; __syncthreads(); }
    float mean = red[0] * (1.f / Hdim);
    __syncthreads();
    float sq = 0.f;
#pragma unroll
    for (int i = 0; i < 3; i++) { float d = vals[i] - mean; sq += d * d; }
    red[tid] = sq; __syncthreads();
    for (int o = 128; o; o >>= 1) { if (tid < o) red[tid] += red[tid + o]; __syncthreads(); }
    float rstd = rsqrtf(red[0] * (1.f / Hdim) + 1e-12f);
#pragma unroll
    for (int i = 0; i < 3; i++) {
        int c = tid + i * 256;
        float v = (vals[i] - mean) * rstd * g[c] + b[c];
        g_x [(size_t)t * Hdim + c] = v;
        g_xr[(size_t)t * Hdim + c] = roundtf(v);
    }
}

// ---------------- residual add + LayerNorm (writes x and xr) ------------------
__global__ __launch_bounds__(256) void add_ln_kernel(
    float* __restrict__ x, const float* __restrict__ y,
    const float* __restrict__ g, const float* __restrict__ b)
{
    int t = blockIdx.x;
    int tid = threadIdx.x;
    float vals[3];
    float sum = 0.f;
#pragma unroll
    for (int i = 0; i < 3; i++) {
        int c = tid + i * 256;
        vals[i] = x[(size_t)t * Hdim + c] + y[(size_t)t * Hdim + c];
        sum += vals[i];
    }
    __shared__ float red[256];
    red[tid] = sum; __syncthreads();
    for (int o = 128; o; o >>= 1) { if (tid < o) red[tid] += red[tid + o]; __syncthreads(); }
    float mean = red[0] * (1.f / Hdim);
    __syncthreads();
    float sq = 0.f;
#pragma unroll
    for (int i = 0; i < 3; i++) { float d = vals[i] - mean; sq += d * d; }
    red[tid] = sq; __syncthreads();
    for (int o = 128; o; o >>= 1) { if (tid < o) red[tid] += red[tid + o]; __syncthreads(); }
    float rstd = rsqrtf(red[0] * (1.f / Hdim) + 1e-12f);
#pragma unroll
    for (int i = 0; i < 3; i++) {
        int c = tid + i * 256;
        float v = (vals[i] - mean) * rstd * g[c] + b[c];
        x[(size_t)t * Hdim + c] = v;
        g_xr[(size_t)t * Hdim + c] = roundtf(v);
    }
}

// ---------------- tf32 GEMM: BM=128 BN=128 BK=16, 256 thr, 4-stage ------------
// A pre-rounded tf32 bits; W raw fp32 (cvt on fragments). rnd=1 rounds outputs.
// 8 warps arranged 2(m) x 4(n); warp tile 64x32.
#define GEMM_STAGES 4
#define GEMM_SMEM   (GEMM_STAGES * (128*20 + 16*136) * 4)   // 75776 bytes
__global__ __launch_bounds__(256, 2) void tf32_gemm_kernel(
    const float* __restrict__ A,
    const float* __restrict__ W0, const float* __restrict__ W1, const float* __restrict__ W2,
    const float* __restrict__ bias0, const float* __restrict__ bias1, const float* __restrict__ bias2,
    float* __restrict__ C0, float* __restrict__ C1, float* __restrict__ C2,
    int M, int N, int K, int act, int rnd)
{
    int z = blockIdx.z;
    const float* W    = (z == 0) ? W0    : (z == 1) ? W1    : W2;
    const float* bias = (z == 0) ? bias0 : (z == 1) ? bias1 : bias2;
    float*       C    = (z == 0) ? C0    : (z == 1) ? C1    : C2;

    extern __shared__ float smem[];
    float (*As)[128][20]  = (float(*)[128][20])smem;                       // 4 stages
    float (*Bs)[16][136]  = (float(*)[16][136])(smem + GEMM_STAGES*128*20);

    int tid = threadIdx.x;
    int warp = tid >> 5, lane = tid & 31;
    int r = lane >> 2, cq = lane & 3;
    int wm = (warp >> 2) * 64;      // 0 / 64
    int wn = (warp & 3) * 32;       // 0,32,64,96
    int m0 = blockIdx.y * 128, n0 = blockIdx.x * 128;

    float acc[4][4][4];
#pragma unroll
    for (int i = 0; i < 4; i++)
#pragma unroll
        for (int j = 0; j < 4; j++)
#pragma unroll
            for (int t = 0; t < 4; t++) acc[i][j][t] = 0.f;

    int KT = K / 16;

    // prologue: stages 0..2
#pragma unroll
    for (int s = 0; s < GEMM_STAGES - 1; s++) {
        int k0 = s * 16;
        {   // A: 128 rows x 16 floats; 2 chunks of 16B per thread
#pragma unroll
            for (int u = 0; u < 2; u++) {
                int f = tid + u * 256;
                int row = f >> 2, seg = (f & 3) * 4;
                unsigned da = (unsigned)__cvta_generic_to_shared(&As[s][row][seg]);
                CPA16(da, A + (size_t)(m0 + row) * K + k0 + seg);
            }
        }
        {   // B: 16 rows x 128 floats; 2 chunks per thread
#pragma unroll
            for (int u = 0; u < 2; u++) {
                int f = tid + u * 256;
                int row = f >> 5, off = (f & 31) * 4;
                unsigned db = (unsigned)__cvta_generic_to_shared(&Bs[s][row][off]);
                CPA16(db, W + (size_t)(k0 + row) * N + n0 + off);
            }
        }
        cp_commit();
    }

    for (int kt = 0; kt < KT; kt++) {
        int cur = kt & (GEMM_STAGES - 1);
        asm volatile("cp.async.wait_group %0;" :: "n"(GEMM_STAGES - 2));
        __syncthreads();

        // refill stage kt+3 (it was released by all warps finishing kt-1)
        if (kt + GEMM_STAGES - 1 < KT) {
            int s = (kt + GEMM_STAGES - 1) & (GEMM_STAGES - 1);
            int k0 = (kt + GEMM_STAGES - 1) * 16;
#pragma unroll
            for (int u = 0; u < 2; u++) {
                int f = tid + u * 256;
                int row = f >> 2, seg = (f & 3) * 4;
                unsigned da = (unsigned)__cvta_generic_to_shared(&As[s][row][seg]);
                CPA16(da, A + (size_t)(m0 + row) * K + k0 + seg);
            }
#pragma unroll
            for (int u = 0; u < 2; u++) {
                int f = tid + u * 256;
                int row = f >> 5, off = (f & 31) * 4;
                unsigned db = (unsigned)__cvta_generic_to_shared(&Bs[s][row][off]);
                CPA16(db, W + (size_t)(k0 + row) * N + n0 + off);
            }
        }
        cp_commit();

#pragma unroll
        for (int ks = 0; ks < 2; ks++) {
            int kk = ks * 8;
            unsigned af[4][4], bf[4][2];
#pragma unroll
            for (int mt = 0; mt < 4; mt++) {
                int mr = wm + mt * 16 + r;
                af[mt][0] = __float_as_uint(As[cur][mr    ][kk + cq]);
                af[mt][1] = __float_as_uint(As[cur][mr + 8][kk + cq]);
                af[mt][2] = __float_as_uint(As[cur][mr    ][kk + cq + 4]);
                af[mt][3] = __float_as_uint(As[cur][mr + 8][kk + cq + 4]);
            }
#pragma unroll
            for (int nt = 0; nt < 4; nt++) {
                int nn = wn + nt * 8 + r;
                bf[nt][0] = f2tf(Bs[cur][kk + cq    ][nn]);
                bf[nt][1] = f2tf(Bs[cur][kk + cq + 4][nn]);
            }
#pragma unroll
            for (int mt = 0; mt < 4; mt++)
#pragma unroll
                for (int nt = 0; nt < 4; nt++)
                    mma8(acc[mt][nt], af[mt][0], af[mt][1], af[mt][2], af[mt][3],
                         bf[nt][0], bf[nt][1]);
        }
    }

    // epilogue
#pragma unroll
    for (int mt = 0; mt < 4; mt++) {
        int row = m0 + wm + mt * 16 + r;
#pragma unroll
        for (int nt = 0; nt < 4; nt++) {
            int col = n0 + wn + nt * 8 + cq * 2;
            float2 bb = *(const float2*)&bias[col];
            float v0 = acc[mt][nt][0] + bb.x;
            float v1 = acc[mt][nt][1] + bb.y;
            float v2 = acc[mt][nt][2] + bb.x;
            float v3 = acc[mt][nt][3] + bb.y;
            if (act) {
                v0 = 0.5f * v0 * (1.0f + erff(v0 * 0.70710678118654752f));
                v1 = 0.5f * v1 * (1.0f + erff(v1 * 0.70710678118654752f));
                v2 = 0.5f * v2 * (1.0f + erff(v2 * 0.70710678118654752f));
                v3 = 0.5f * v3 * (1.0f + erff(v3 * 0.70710678118654752f));
            }
            if (rnd) {
                v0 = roundtf(v0); v1 = roundtf(v1);
                v2 = roundtf(v2); v3 = roundtf(v3);
            }
            *(float2*)&C[(size_t)row * N + col]       = make_float2(v0, v1);
            *(float2*)&C[(size_t)(row + 8) * N + col] = make_float2(v2, v3);
        }
    }
}

// ---------------- attention-mask bias -----------------------------------------
__global__ void abias_kernel(const int* __restrict__ mask)
{
    int i = blockIdx.x * blockDim.x + threadIdx.x;
    if (i < BATCH * SEQ) g_abias[i] = (1.f - (float)mask[i]) * -10000.f;
}

// ---------------- fused scores + softmax --------------------------------------
__global__ __launch_bounds__(256) void scores_softmax_kernel(
    const float* __restrict__ q, const float* __restrict__ k)
{
    extern __shared__ float sm[];
    float (*Qs)[68] = (float(*)[68])sm;                    // 64x68
    float (*Ks)[64][68] = (float(*)[64][68])(sm + 64*68);  // [2][64][68]
    float (*S)[520] = (float(*)[520])(sm + 3*64*68);       // 64x520

    int bh = blockIdx.y;
    int b = bh / NHEADS, h = bh - b * NHEADS;
    int i0 = blockIdx.x * 64;
    int tid = threadIdx.x;
    int warp = tid >> 5, lane = tid & 31;
    int r = lane >> 2, cq = lane & 3;
    int wm = (warp >> 2) * 32;      // 0 / 32
    int wn = (warp & 3) * 16;       // 0,16,32,48

    // load Q tile
#pragma unroll
    for (int u = 0; u < 2; u++) {
        int c = tid + u * 256;
        int row = c >> 3, off = (c & 7) << 3;
        float4 v0 = *(const float4*)(q + (size_t)(b * SEQ + i0 + row) * Hdim + h * DHEAD + off);
        float4 v1 = *(const float4*)(q + (size_t)(b * SEQ + i0 + row) * Hdim + h * DHEAD + off + 4);
        *(float4*)&Qs[row][off]     = v0;
        *(float4*)&Qs[row][off + 4] = v1;
    }
    __syncthreads();

    // Q fragments in registers
    unsigned aq[8][2][4];
#pragma unroll
    for (int ks = 0; ks < 8; ks++) {
        int kk = ks * 8;
#pragma unroll
        for (int mt = 0; mt < 2; mt++) {
            int mr = wm + mt * 16 + r;
            aq[ks][mt][0] = __float_as_uint(Qs[mr    ][kk + cq]);
            aq[ks][mt][1] = __float_as_uint(Qs[mr + 8][kk + cq]);
            aq[ks][mt][2] = __float_as_uint(Qs[mr    ][kk + cq + 4]);
            aq[ks][mt][3] = __float_as_uint(Qs[mr + 8][kk + cq + 4]);
        }
    }

    // prologue K tile 0
    {
#pragma unroll
        for (int u = 0; u < 2; u++) {
            int c = tid + u * 256;
            int row = c >> 3, off = (c & 7) << 3;
            const float* src = k + (size_t)(b * SEQ + row) * Hdim + h * DHEAD + off;
            unsigned d = (unsigned)__cvta_generic_to_shared(&Ks[0][row][off]);
            CPA16(d, src); CPA16(d + 16, src + 4);
        }
        cp_commit();
    }

    for (int jt = 0; jt < 8; jt++) {
        int cur = jt & 1;
        __syncthreads();
        if (jt + 1 < 8) {
            int j0 = (jt + 1) * 64;
#pragma unroll
            for (int u = 0; u < 2; u++) {
                int c = tid + u * 256;
                int row = c >> 3, off = (c & 7) << 3;
                const float* src = k + (size_t)(b * SEQ + j0 + row) * Hdim + h * DHEAD + off;
                unsigned d = (unsigned)__cvta_generic_to_shared(&Ks[cur ^ 1][row][off]);
                CPA16(d, src); CPA16(d + 16, src + 4);
            }
        }
        cp_commit();
        asm volatile("cp.async.wait_group 1;");
        __syncthreads();

        float acc[2][2][4];
#pragma unroll
        for (int i = 0; i < 2; i++)
#pragma unroll
            for (int j = 0; j < 2; j++)
#pragma unroll
                for (int t = 0; t < 4; t++) acc[i][j][t] = 0.f;

#pragma unroll
        for (int ks = 0; ks < 8; ks++) {
            int kk = ks * 8;
            unsigned bf[2][2];
#pragma unroll
            for (int nt = 0; nt < 2; nt++) {
                int nn = wn + nt * 8 + r;
                bf[nt][0] = __float_as_uint(Ks[cur][nn][kk + cq]);
                bf[nt][1] = __float_as_uint(Ks[cur][nn][kk + cq + 4]);
            }
#pragma unroll
            for (int mt = 0; mt < 2; mt++)
#pragma unroll
                for (int nt = 0; nt < 2; nt++)
                    mma8(acc[mt][nt], aq[ks][mt][0], aq[ks][mt][1],
                         aq[ks][mt][2], aq[ks][mt][3], bf[nt][0], bf[nt][1]);
        }

        // write S tile with scale + mask bias
#pragma unroll
        for (int mt = 0; mt < 2; mt++) {
            int row = wm + mt * 16 + r;
#pragma unroll
            for (int nt = 0; nt < 2; nt++) {
                int jcol = jt * 64 + wn + nt * 8 + cq * 2;
                float2 ab = *(const float2*)&g_abias[b * SEQ + jcol];
                *(float2*)&S[row][jcol] =
                    make_float2(acc[mt][nt][0] * 0.125f + ab.x,
                                acc[mt][nt][1] * 0.125f + ab.y);
                *(float2*)&S[row + 8][jcol] =
                    make_float2(acc[mt][nt][2] * 0.125f + ab.x,
                                acc[mt][nt][3] * 0.125f + ab.y);
            }
        }
    }
    __syncthreads();

    // softmax: warp w handles rows w*8 .. w*8+7
#pragma unroll
    for (int rr = 0; rr < 8; rr++) {
        int row = warp * 8 + rr;
        float vals[16];
        float m = -1e30f;
#pragma unroll
        for (int t = 0; t < 16; t++) {
            vals[t] = S[row][lane + t * 32];
            m = fmaxf(m, vals[t]);
        }
#pragma unroll
        for (int off = 16; off; off >>= 1) m = fmaxf(m, __shfl_xor_sync(0xFFFFFFFFu, m, off));
        float s = 0.f;
#pragma unroll
        for (int t = 0; t < 16; t++) { vals[t] = expf(vals[t] - m); s += vals[t]; }
#pragma unroll
        for (int off = 16; off; off >>= 1) s += __shfl_xor_sync(0xFFFFFFFFu, s, off);
        float inv = 1.f / s;
        float* o = &g_scores[((size_t)bh * SEQ + i0 + row) * SEQ];
#pragma unroll
        for (int t = 0; t < 16; t++)
            o[lane + t * 32] = roundtf(vals[t] * inv);
    }
}

// ---------------- ctx (tf32): per (b,h) attn(512x512) @ V(512x64) -------------
__global__ __launch_bounds__(128) void attn_ctx_tf32(
    const float* __restrict__ attn, const float* __restrict__ v,
    float* __restrict__ ctx)
{
    __shared__ float As[2][128][20];
    __shared__ float Bs[2][16][72];
    int bh = blockIdx.y;
    int b = bh / NHEADS, h = bh - b * NHEADS;
    int m0 = blockIdx.x * 128;
    const float* A = attn + (size_t)bh * SEQ * SEQ;
    const float* V = v + (size_t)b * SEQ * Hdim + h * DHEAD;

    int tid = threadIdx.x;
    int warp = tid >> 5, lane = tid & 31;
    int r = lane >> 2, cq = lane & 3;
    int wm = (warp >> 1) * 64, wn = (warp & 1) * 32;

    float acc[4][4][4];
#pragma unroll
    for (int i = 0; i < 4; i++)
#pragma unroll
        for (int j = 0; j < 4; j++)
#pragma unroll
            for (int t = 0; t < 4; t++) acc[i][j][t] = 0.f;

    {
        const float* a = A + (size_t)(m0 + tid) * SEQ;
        unsigned da = (unsigned)__cvta_generic_to_shared(&As[0][tid][0]);
        CPA16(da, a); CPA16(da + 16, a + 4); CPA16(da + 32, a + 8); CPA16(da + 48, a + 12);
#pragma unroll
        for (int u = 0; u < 2; u++) {
            int c = tid + u * 128;
            int row = c >> 4, off = (c & 15) << 2;
            unsigned db = (unsigned)__cvta_generic_to_shared(&Bs[0][row][off]);
            CPA16(db, V + (size_t)row * Hdim + off);
        }
        cp_commit();
    }

    const int KT = SEQ / 16;
    for (int kt = 0; kt < KT; kt++) {
        int cur = kt & 1;
        __syncthreads();
        if (kt + 1 < KT) {
            int k0 = (kt + 1) * 16;
            const float* a = A + (size_t)(m0 + tid) * SEQ + k0;
            unsigned da = (unsigned)__cvta_generic_to_shared(&As[cur ^ 1][tid][0]);
            CPA16(da, a); CPA16(da + 16, a + 4); CPA16(da + 32, a + 8); CPA16(da + 48, a + 12);
#pragma unroll
            for (int u = 0; u < 2; u++) {
                int c = tid + u * 128;
                int row = c >> 4, off = (c & 15) << 2;
                unsigned db = (unsigned)__cvta_generic_to_shared(&Bs[cur ^ 1][row][off]);
                CPA16(db, V + (size_t)(k0 + row) * Hdim + off);
            }
        }
        cp_commit();
        asm volatile("cp.async.wait_group 1;");
        __syncthreads();

#pragma unroll
        for (int ks = 0; ks < 2; ks++) {
            int kk = ks * 8;
            unsigned af[4][4], bf[4][2];
#pragma unroll
            for (int mt = 0; mt < 4; mt++) {
                int mr = wm + mt * 16 + r;
                af[mt][0] = __float_as_uint(As[cur][mr    ][kk + cq]);
                af[mt][1] = __float_as_uint(As[cur][mr + 8][kk + cq]);
                af[mt][2] = __float_as_uint(As[cur][mr    ][kk + cq + 4]);
                af[mt][3] = __float_as_uint(As[cur][mr + 8][kk + cq + 4]);
            }
#pragma unroll
            for (int nt = 0; nt < 4; nt++) {
                int nn = wn + nt * 8 + r;
                bf[nt][0] = __float_as_uint(Bs[cur][kk + cq    ][nn]);
                bf[nt][1] = __float_as_uint(Bs[cur][kk + cq + 4][nn]);
            }
#pragma unroll
            for (int mt = 0; mt < 4; mt++)
#pragma unroll
                for (int nt = 0; nt < 4; nt++)
                    mma8(acc[mt][nt], af[mt][0], af[mt][1], af[mt][2], af[mt][3],
                         bf[nt][0], bf[nt][1]);
        }
    }

#pragma unroll
    for (int mt = 0; mt < 4; mt++) {
        int irow = b * SEQ + m0 + wm + mt * 16 + r;
#pragma unroll
        for (int nt = 0; nt < 4; nt++) {
            int col = h * DHEAD + wn + nt * 8 + cq * 2;
            *(float2*)&ctx[(size_t)irow * Hdim + col] =
                make_float2(roundtf(acc[mt][nt][0]), roundtf(acc[mt][nt][1]));
            *(float2*)&ctx[(size_t)(irow + 8) * Hdim + col] =
                make_float2(roundtf(acc[mt][nt][2]), roundtf(acc[mt][nt][3]));
        }
    }
}

// ---------------- heads: entity logits + pi/pj for relations ------------------
__global__ __launch_bounds__(256) void heads_kernel(
    const float* __restrict__ x, const float* __restrict__ W_ent,
    const float* __restrict__ b_ent, const float* __restrict__ W_rel,
    const float* __restrict__ b_rel, float* __restrict__ ent_out)
{
    int t = blockIdx.x;
    int tid = threadIdx.x;
    __shared__ float xs[Hdim];
    for (int i = tid; i < Hdim; i += 256) xs[i] = x[(size_t)t * Hdim + i];
    __syncthreads();
    int warp = tid >> 5, lane = tid & 31;
    for (int o = warp; o < NEnt + 2 * NRel; o += 8) {
        float s = 0.f;
        if (o < NEnt) {
            for (int k = lane; k < Hdim; k += 32) s += xs[k] * W_ent[(size_t)k * NEnt + o];
        } else if (o < NEnt + NRel) {
            int rr = o - NEnt;
            for (int k = lane; k < Hdim; k += 32) s += xs[k] * W_rel[(size_t)k * NRel + rr];
        } else {
            int rr = o - NEnt - NRel;
            for (int k = lane; k < Hdim; k += 32) s += xs[k] * W_rel[(size_t)(Hdim + k) * NRel + rr];
        }
#pragma unroll
        for (int off = 16; off; off >>= 1) s += __shfl_xor_sync(0xFFFFFFFFu, s, off);
        if (lane == 0) {
            if (o < NEnt)             ent_out[(size_t)t * NEnt + o] = s + b_ent[o];
            else if (o < NEnt + NRel) g_pi[t * NRel + (o - NEnt)] = s;
            else                      g_pj[t * NRel + (o - NEnt - NRel)] = s + b_rel[o - NEnt - NRel];
        }
    }
}

// ---------------- relation broadcast ------------------------------------------
__global__ __launch_bounds__(256) void relation_kernel(float* __restrict__ out)
{
    int bi = blockIdx.x;
    int b = bi >> 9;
    __shared__ float ps[NRel];
    if (threadIdx.x < NRel) ps[threadIdx.x] = g_pi[bi * NRel + threadIdx.x];
    __syncthreads();
    const float* pjb = g_pj + (size_t)(b << 9) * NRel;
    float* o = out + (size_t)bi * SEQ * NRel;
    for (int idx = threadIdx.x; idx < SEQ * NRel; idx += 256) {
        int r = idx % NRel;
        o[idx] = ps[r] + pjb[idx];
    }
}

// ---------------- host orchestration -----------------------------------------
extern "C" void kernel_launch(void* const* d_in, const int* in_sizes, int n_in,
                              void* d_out, int out_size)
{
    const int*   input_ids = (const int*)  d_in[0];
    const int*   attn_mask = (const int*)  d_in[1];
    const float* emb_word  = (const float*)d_in[2];
    const float* emb_pos   = (const float*)d_in[3];
    const float* emb_type  = (const float*)d_in[4];
    const float* emb_ln_g  = (const float*)d_in[5];
    const float* emb_ln_b  = (const float*)d_in[6];
    const float* Wq = (const float*)d_in[7];
    const float* bq = (const float*)d_in[8];
    const float* Wk = (const float*)d_in[9];
    const float* bk = (const float*)d_in[10];
    const float* Wv = (const float*)d_in[11];
    const float* bv = (const float*)d_in[12];
    const float* Wo = (const float*)d_in[13];
    const float* bo = (const float*)d_in[14];
    const float* ln1_g = (const float*)d_in[15];
    const float* ln1_b = (const float*)d_in[16];
    const float* W1 = (const float*)d_in[17];
    const float* b1 = (const float*)d_in[18];
    const float* W2 = (const float*)d_in[19];
    const float* b2 = (const float*)d_in[20];
    const float* ln2_g = (const float*)d_in[21];
    const float* ln2_b = (const float*)d_in[22];
    const float* W_ent = (const float*)d_in[23];
    const float* b_ent = (const float*)d_in[24];
    const float* W_rel = (const float*)d_in[25];
    const float* b_rel = (const float*)d_in[26];

    float *x, *xr, *q, *k, *v, *ctx, *ffn, *sc;
    cudaGetSymbolAddress((void**)&x,   g_x);
    cudaGetSymbolAddress((void**)&xr,  g_xr);
    cudaGetSymbolAddress((void**)&q,   g_q);
    cudaGetSymbolAddress((void**)&k,   g_k);
    cudaGetSymbolAddress((void**)&v,   g_v);
    cudaGetSymbolAddress((void**)&ctx, g_ctx);
    cudaGetSymbolAddress((void**)&ffn, g_ffn);
    cudaGetSymbolAddress((void**)&sc,  g_scores);

    cudaFuncSetAttribute(scores_softmax_kernel,
                         cudaFuncAttributeMaxDynamicSharedMemorySize, 185344);
    cudaFuncSetAttribute(tf32_gemm_kernel,
                         cudaFuncAttributeMaxDynamicSharedMemorySize, GEMM_SMEM);

    embed_ln_kernel<<<MTOK, 256>>>(input_ids, emb_word, emb_pos, emb_type,
                                   emb_ln_g, emb_ln_b);
    abias_kernel<<<(BATCH * SEQ + 255) / 256, 256>>>(attn_mask);

    dim3 gQKV(Hdim / 128, MTOK / 128, 3);
    dim3 gH(Hdim / 128, MTOK / 128, 1);
    dim3 gF1(FFdim / 128, MTOK / 128, 1);
    dim3 gSS(SEQ / 64, BATCH * NHEADS);
    dim3 gC(SEQ / 128, BATCH * NHEADS);

    for (int l = 0; l < NLAY; l++) {
        size_t wHH = (size_t)l * Hdim * Hdim;
        size_t wH  = (size_t)l * Hdim;
        size_t wHF = (size_t)l * Hdim * FFdim;
        tf32_gemm_kernel<<<gQKV, 256, GEMM_SMEM>>>(xr, Wq + wHH, Wk + wHH, Wv + wHH,
                                        bq + wH, bk + wH, bv + wH,
                                        q, k, v, MTOK, Hdim, Hdim, 0, 1);
        scores_softmax_kernel<<<gSS, 256, 185344>>>(q, k);
        attn_ctx_tf32<<<gC, 128>>>(sc, v, ctx);
        tf32_gemm_kernel<<<gH, 256, GEMM_SMEM>>>(ctx, Wo + wHH, Wo + wHH, Wo + wHH,
                                      bo + wH, bo + wH, bo + wH,
                                      q, q, q, MTOK, Hdim, Hdim, 0, 0);
        add_ln_kernel<<<MTOK, 256>>>(x, q, ln1_g + wH, ln1_b + wH);
        tf32_gemm_kernel<<<gF1, 256, GEMM_SMEM>>>(xr, W1 + wHF, W1 + wHF, W1 + wHF,
                                       b1 + (size_t)l * FFdim, b1 + (size_t)l * FFdim, b1 + (size_t)l * FFdim,
                                       ffn, ffn, ffn, MTOK, FFdim, Hdim, 1, 1);
        tf32_gemm_kernel<<<gH, 256, GEMM_SMEM>>>(ffn, W2 + wHF, W2 + wHF, W2 + wHF,
                                      b2 + wH, b2 + wH, b2 + wH,
                                      q, q, q, MTOK, Hdim, FFdim, 0, 0);
        add_ln_kernel<<<MTOK, 256>>>(x, q, ln2_g + wH, ln2_b + wH);
    }

    float* out = (float*)d_out;
    heads_kernel<<<MTOK, 256>>>(x, W_ent, b_ent, W_rel, b_rel, out);
    relation_kernel<<<MTOK, 256>>>(out + (size_t)MTOK * NEnt);
}

// round 8
// speedup vs baseline: 1.0133x; 1.0133x over previous
#include <cuda_runtime.h>
#include <math.h>

#define Hdim   768
#define FFdim  3072
#define NLAY   12
#define NHEADS 12
#define DHEAD  64
#define BATCH  4
#define SEQ    512
#define MTOK   (BATCH*SEQ)   // 2048
#define NEnt   12
#define NRel   13

// ---------------- scratch (static device globals; no allocation) -------------
__device__ float g_x[MTOK*Hdim];
__device__ float g_xr[MTOK*Hdim];      // tf32-rounded copy of x (GEMM A side)
__device__ float g_q[MTOK*Hdim];
__device__ float g_k[MTOK*Hdim];
__device__ float g_v[MTOK*Hdim];
__device__ float g_ctx[MTOK*Hdim];
__device__ float g_ffn[MTOK*FFdim];
__device__ float g_pi[MTOK*NRel];
__device__ float g_pj[MTOK*NRel];
__device__ float g_abias[BATCH*SEQ];

// ---------------- tf32 helpers ------------------------------------------------
__device__ __forceinline__ unsigned f2tf(float f) {
    unsigned u;
    asm("cvt.rna.tf32.f32 %0, %1;" : "=r"(u) : "f"(f));
    return u;
}
__device__ __forceinline__ float roundtf(float f) { return __uint_as_float(f2tf(f)); }
__device__ __forceinline__ void mma8(float* c, unsigned a0, unsigned a1,
                                     unsigned a2, unsigned a3,
                                     unsigned b0, unsigned b1) {
    asm volatile(
        "mma.sync.aligned.m16n8k8.row.col.f32.tf32.tf32.f32 "
        "{%0,%1,%2,%3},{%4,%5,%6,%7},{%8,%9},{%0,%1,%2,%3};"
        : "+f"(c[0]), "+f"(c[1]), "+f"(c[2]), "+f"(c[3])
        : "r"(a0), "r"(a1), "r"(a2), "r"(a3), "r"(b0), "r"(b1));
}
#define CPA16(dst, src) \
    asm volatile("cp.async.ca.shared.global [%0], [%1], 16;" :: "r"(dst), "l"(src))
__device__ __forceinline__ void cp_commit() { asm volatile("cp.async.commit_group;"); }

// ---------------- embedding + LayerNorm ---------------------------------------
__global__ __launch_bounds__(256) void embed_ln_kernel(
    const int* __restrict__ ids, const float* __restrict__ ew,
    const float* __restrict__ ep, const float* __restrict__ et,
    const float* __restrict__ g, const float* __restrict__ b)
{
    int t = blockIdx.x;
    int s = t & (SEQ - 1);
    int id = ids[t];
    int tid = threadIdx.x;
    float vals[3];
    float sum = 0.f;
#pragma unroll
    for (int i = 0; i < 3; i++) {
        int c = tid + i * 256;
        vals[i] = ew[(size_t)id * Hdim + c] + ep[(size_t)s * Hdim + c] + et[c];
        sum += vals[i];
    }
    __shared__ float red[256];
    red[tid] = sum; __syncthreads();
    for (int o = 128; o; o >>= 1) { if (tid < o) red[tid] += red[tid + o]; __syncthreads(); }
    float mean = red[0] * (1.f / Hdim);
    __syncthreads();
    float sq = 0.f;
#pragma unroll
    for (int i = 0; i < 3; i++) { float d = vals[i] - mean; sq += d * d; }
    red[tid] = sq; __syncthreads();
    for (int o = 128; o; o >>= 1) { if (tid < o) red[tid] += red[tid + o]; __syncthreads(); }
    float rstd = rsqrtf(red[0] * (1.f / Hdim) + 1e-12f);
#pragma unroll
    for (int i = 0; i < 3; i++) {
        int c = tid + i * 256;
        float v = (vals[i] - mean) * rstd * g[c] + b[c];
        g_x [(size_t)t * Hdim + c] = v;
        g_xr[(size_t)t * Hdim + c] = roundtf(v);
    }
}

// ---------------- residual add + LayerNorm (writes x and xr) ------------------
__global__ __launch_bounds__(256) void add_ln_kernel(
    float* __restrict__ x, const float* __restrict__ y,
    const float* __restrict__ g, const float* __restrict__ b)
{
    int t = blockIdx.x;
    int tid = threadIdx.x;
    float vals[3];
    float sum = 0.f;
#pragma unroll
    for (int i = 0; i < 3; i++) {
        int c = tid + i * 256;
        vals[i] = x[(size_t)t * Hdim + c] + y[(size_t)t * Hdim + c];
        sum += vals[i];
    }
    __shared__ float red[256];
    red[tid] = sum; __syncthreads();
    for (int o = 128; o; o >>= 1) { if (tid < o) red[tid] += red[tid + o]; __syncthreads(); }
    float mean = red[0] * (1.f / Hdim);
    __syncthreads();
    float sq = 0.f;
#pragma unroll
    for (int i = 0; i < 3; i++) { float d = vals[i] - mean; sq += d * d; }
    red[tid] = sq; __syncthreads();
    for (int o = 128; o; o >>= 1) { if (tid < o) red[tid] += red[tid + o]; __syncthreads(); }
    float rstd = rsqrtf(red[0] * (1.f / Hdim) + 1e-12f);
#pragma unroll
    for (int i = 0; i < 3; i++) {
        int c = tid + i * 256;
        float v = (vals[i] - mean) * rstd * g[c] + b[c];
        x[(size_t)t * Hdim + c] = v;
        g_xr[(size_t)t * Hdim + c] = roundtf(v);
    }
}

// ---------------- tf32 GEMM: BM=128 BN=128 BK=16, 256 thr, 4-stage ------------
#define GEMM_STAGES 4
#define GEMM_SMEM   (GEMM_STAGES * (128*20 + 16*136) * 4)   // 75776 bytes
__global__ __launch_bounds__(256, 2) void tf32_gemm_kernel(
    const float* __restrict__ A,
    const float* __restrict__ W0, const float* __restrict__ W1, const float* __restrict__ W2,
    const float* __restrict__ bias0, const float* __restrict__ bias1, const float* __restrict__ bias2,
    float* __restrict__ C0, float* __restrict__ C1, float* __restrict__ C2,
    int M, int N, int K, int act, int rnd)
{
    int z = blockIdx.z;
    const float* W    = (z == 0) ? W0    : (z == 1) ? W1    : W2;
    const float* bias = (z == 0) ? bias0 : (z == 1) ? bias1 : bias2;
    float*       C    = (z == 0) ? C0    : (z == 1) ? C1    : C2;

    extern __shared__ float smem[];
    float (*As)[128][20]  = (float(*)[128][20])smem;
    float (*Bs)[16][136]  = (float(*)[16][136])(smem + GEMM_STAGES*128*20);

    int tid = threadIdx.x;
    int warp = tid >> 5, lane = tid & 31;
    int r = lane >> 2, cq = lane & 3;
    int wm = (warp >> 2) * 64;
    int wn = (warp & 3) * 32;
    int m0 = blockIdx.y * 128, n0 = blockIdx.x * 128;

    float acc[4][4][4];
#pragma unroll
    for (int i = 0; i < 4; i++)
#pragma unroll
        for (int j = 0; j < 4; j++)
#pragma unroll
            for (int t = 0; t < 4; t++) acc[i][j][t] = 0.f;

    int KT = K / 16;

#pragma unroll
    for (int s = 0; s < GEMM_STAGES - 1; s++) {
        int k0 = s * 16;
#pragma unroll
        for (int u = 0; u < 2; u++) {
            int f = tid + u * 256;
            int row = f >> 2, seg = (f & 3) * 4;
            unsigned da = (unsigned)__cvta_generic_to_shared(&As[s][row][seg]);
            CPA16(da, A + (size_t)(m0 + row) * K + k0 + seg);
        }
#pragma unroll
        for (int u = 0; u < 2; u++) {
            int f = tid + u * 256;
            int row = f >> 5, off = (f & 31) * 4;
            unsigned db = (unsigned)__cvta_generic_to_shared(&Bs[s][row][off]);
            CPA16(db, W + (size_t)(k0 + row) * N + n0 + off);
        }
        cp_commit();
    }

    for (int kt = 0; kt < KT; kt++) {
        int cur = kt & (GEMM_STAGES - 1);
        asm volatile("cp.async.wait_group %0;" :: "n"(GEMM_STAGES - 2));
        __syncthreads();

        if (kt + GEMM_STAGES - 1 < KT) {
            int s = (kt + GEMM_STAGES - 1) & (GEMM_STAGES - 1);
            int k0 = (kt + GEMM_STAGES - 1) * 16;
#pragma unroll
            for (int u = 0; u < 2; u++) {
                int f = tid + u * 256;
                int row = f >> 2, seg = (f & 3) * 4;
                unsigned da = (unsigned)__cvta_generic_to_shared(&As[s][row][seg]);
                CPA16(da, A + (size_t)(m0 + row) * K + k0 + seg);
            }
#pragma unroll
            for (int u = 0; u < 2; u++) {
                int f = tid + u * 256;
                int row = f >> 5, off = (f & 31) * 4;
                unsigned db = (unsigned)__cvta_generic_to_shared(&Bs[s][row][off]);
                CPA16(db, W + (size_t)(k0 + row) * N + n0 + off);
            }
        }
        cp_commit();

#pragma unroll
        for (int ks = 0; ks < 2; ks++) {
            int kk = ks * 8;
            unsigned af[4][4], bf[4][2];
#pragma unroll
            for (int mt = 0; mt < 4; mt++) {
                int mr = wm + mt * 16 + r;
                af[mt][0] = __float_as_uint(As[cur][mr    ][kk + cq]);
                af[mt][1] = __float_as_uint(As[cur][mr + 8][kk + cq]);
                af[mt][2] = __float_as_uint(As[cur][mr    ][kk + cq + 4]);
                af[mt][3] = __float_as_uint(As[cur][mr + 8][kk + cq + 4]);
            }
#pragma unroll
            for (int nt = 0; nt < 4; nt++) {
                int nn = wn + nt * 8 + r;
                bf[nt][0] = f2tf(Bs[cur][kk + cq    ][nn]);
                bf[nt][1] = f2tf(Bs[cur][kk + cq + 4][nn]);
            }
#pragma unroll
            for (int mt = 0; mt < 4; mt++)
#pragma unroll
                for (int nt = 0; nt < 4; nt++)
                    mma8(acc[mt][nt], af[mt][0], af[mt][1], af[mt][2], af[mt][3],
                         bf[nt][0], bf[nt][1]);
        }
    }

#pragma unroll
    for (int mt = 0; mt < 4; mt++) {
        int row = m0 + wm + mt * 16 + r;
#pragma unroll
        for (int nt = 0; nt < 4; nt++) {
            int col = n0 + wn + nt * 8 + cq * 2;
            float2 bb = *(const float2*)&bias[col];
            float v0 = acc[mt][nt][0] + bb.x;
            float v1 = acc[mt][nt][1] + bb.y;
            float v2 = acc[mt][nt][2] + bb.x;
            float v3 = acc[mt][nt][3] + bb.y;
            if (act) {
                v0 = 0.5f * v0 * (1.0f + erff(v0 * 0.70710678118654752f));
                v1 = 0.5f * v1 * (1.0f + erff(v1 * 0.70710678118654752f));
                v2 = 0.5f * v2 * (1.0f + erff(v2 * 0.70710678118654752f));
                v3 = 0.5f * v3 * (1.0f + erff(v3 * 0.70710678118654752f));
            }
            if (rnd) {
                v0 = roundtf(v0); v1 = roundtf(v1);
                v2 = roundtf(v2); v3 = roundtf(v3);
            }
            *(float2*)&C[(size_t)row * N + col]       = make_float2(v0, v1);
            *(float2*)&C[(size_t)(row + 8) * N + col] = make_float2(v2, v3);
        }
    }
}

// ---------------- tf32 GEMM: BM=64 BN=128 BK=16, 256 thr, 4-stage -------------
// For N=768 GEMMs (O-proj, FF2): doubles grid to 192 blocks, 2 blocks/SM.
#define G64_STAGES 4
#define G64_SMEM   (G64_STAGES * (64*20 + 16*136) * 4)   // 55296 bytes
__global__ __launch_bounds__(256, 2) void tf32_gemm64_kernel(
    const float* __restrict__ A, const float* __restrict__ W,
    const float* __restrict__ bias, float* __restrict__ C,
    int M, int N, int K, int act, int rnd)
{
    extern __shared__ float smem[];
    float (*As)[64][20]  = (float(*)[64][20])smem;
    float (*Bs)[16][136] = (float(*)[16][136])(smem + G64_STAGES*64*20);

    int tid = threadIdx.x;
    int warp = tid >> 5, lane = tid & 31;
    int r = lane >> 2, cq = lane & 3;
    int wm = (warp >> 2) * 32;
    int wn = (warp & 3) * 32;
    int m0 = blockIdx.y * 64, n0 = blockIdx.x * 128;

    float acc[2][4][4];
#pragma unroll
    for (int i = 0; i < 2; i++)
#pragma unroll
        for (int j = 0; j < 4; j++)
#pragma unroll
            for (int t = 0; t < 4; t++) acc[i][j][t] = 0.f;

    int KT = K / 16;

#pragma unroll
    for (int s = 0; s < G64_STAGES - 1; s++) {
        int k0 = s * 16;
        {
            int row = tid >> 2, seg = (tid & 3) * 4;
            unsigned da = (unsigned)__cvta_generic_to_shared(&As[s][row][seg]);
            CPA16(da, A + (size_t)(m0 + row) * K + k0 + seg);
        }
#pragma unroll
        for (int u = 0; u < 2; u++) {
            int f = tid + u * 256;
            int row = f >> 5, off = (f & 31) * 4;
            unsigned db = (unsigned)__cvta_generic_to_shared(&Bs[s][row][off]);
            CPA16(db, W + (size_t)(k0 + row) * N + n0 + off);
        }
        cp_commit();
    }

    for (int kt = 0; kt < KT; kt++) {
        int cur = kt & (G64_STAGES - 1);
        asm volatile("cp.async.wait_group %0;" :: "n"(G64_STAGES - 2));
        __syncthreads();

        if (kt + G64_STAGES - 1 < KT) {
            int s = (kt + G64_STAGES - 1) & (G64_STAGES - 1);
            int k0 = (kt + G64_STAGES - 1) * 16;
            {
                int row = tid >> 2, seg = (tid & 3) * 4;
                unsigned da = (unsigned)__cvta_generic_to_shared(&As[s][row][seg]);
                CPA16(da, A + (size_t)(m0 + row) * K + k0 + seg);
            }
#pragma unroll
            for (int u = 0; u < 2; u++) {
                int f = tid + u * 256;
                int row = f >> 5, off = (f & 31) * 4;
                unsigned db = (unsigned)__cvta_generic_to_shared(&Bs[s][row][off]);
                CPA16(db, W + (size_t)(k0 + row) * N + n0 + off);
            }
        }
        cp_commit();

#pragma unroll
        for (int ks = 0; ks < 2; ks++) {
            int kk = ks * 8;
            unsigned af[2][4], bf[4][2];
#pragma unroll
            for (int mt = 0; mt < 2; mt++) {
                int mr = wm + mt * 16 + r;
                af[mt][0] = __float_as_uint(As[cur][mr    ][kk + cq]);
                af[mt][1] = __float_as_uint(As[cur][mr + 8][kk + cq]);
                af[mt][2] = __float_as_uint(As[cur][mr    ][kk + cq + 4]);
                af[mt][3] = __float_as_uint(As[cur][mr + 8][kk + cq + 4]);
            }
#pragma unroll
            for (int nt = 0; nt < 4; nt++) {
                int nn = wn + nt * 8 + r;
                bf[nt][0] = f2tf(Bs[cur][kk + cq    ][nn]);
                bf[nt][1] = f2tf(Bs[cur][kk + cq + 4][nn]);
            }
#pragma unroll
            for (int mt = 0; mt < 2; mt++)
#pragma unroll
                for (int nt = 0; nt < 4; nt++)
                    mma8(acc[mt][nt], af[mt][0], af[mt][1], af[mt][2], af[mt][3],
                         bf[nt][0], bf[nt][1]);
        }
    }

#pragma unroll
    for (int mt = 0; mt < 2; mt++) {
        int row = m0 + wm + mt * 16 + r;
#pragma unroll
        for (int nt = 0; nt < 4; nt++) {
            int col = n0 + wn + nt * 8 + cq * 2;
            float2 bb = *(const float2*)&bias[col];
            float v0 = acc[mt][nt][0] + bb.x;
            float v1 = acc[mt][nt][1] + bb.y;
            float v2 = acc[mt][nt][2] + bb.x;
            float v3 = acc[mt][nt][3] + bb.y;
            if (act) {
                v0 = 0.5f * v0 * (1.0f + erff(v0 * 0.70710678118654752f));
                v1 = 0.5f * v1 * (1.0f + erff(v1 * 0.70710678118654752f));
                v2 = 0.5f * v2 * (1.0f + erff(v2 * 0.70710678118654752f));
                v3 = 0.5f * v3 * (1.0f + erff(v3 * 0.70710678118654752f));
            }
            if (rnd) {
                v0 = roundtf(v0); v1 = roundtf(v1);
                v2 = roundtf(v2); v3 = roundtf(v3);
            }
            *(float2*)&C[(size_t)row * N + col]       = make_float2(v0, v1);
            *(float2*)&C[(size_t)(row + 8) * N + col] = make_float2(v2, v3);
        }
    }
}

// ---------------- attention-mask bias -----------------------------------------
__global__ void abias_kernel(const int* __restrict__ mask)
{
    int i = blockIdx.x * blockDim.x + threadIdx.x;
    if (i < BATCH * SEQ) g_abias[i] = (1.f - (float)mask[i]) * -10000.f;
}

// ---------------- fused attention: scores + softmax + P@V ---------------------
// grid (SEQ/64, B*NH), 256 thr. Q frags in regs; K then V stream through the
// same double buffers; S (64x516) lives in smem; probabilities never touch gmem.
#define ATTN_SMEM ((64*68 + 2*64*68 + 64*516) * 4)   // 184320 bytes
__global__ __launch_bounds__(256) void attn_fused_kernel(
    const float* __restrict__ q, const float* __restrict__ k,
    const float* __restrict__ v, float* __restrict__ ctx)
{
    extern __shared__ float sm[];
    float (*Qs)[68]     = (float(*)[68])sm;                     // 64x68
    float (*Ks)[64][68] = (float(*)[64][68])(sm + 64*68);       // [2][64][68] (K, then V)
    float (*S)[516]     = (float(*)[516])(sm + 3*64*68);        // 64x516

    int bh = blockIdx.y;
    int b = bh / NHEADS, h = bh - b * NHEADS;
    int i0 = blockIdx.x * 64;
    int tid = threadIdx.x;
    int warp = tid >> 5, lane = tid & 31;
    int r = lane >> 2, cq = lane & 3;
    int wm = (warp >> 2) * 32;      // scores phase: 2 m-warps
    int wn = (warp & 3) * 16;       // scores phase: 4 n-warps

    // load Q tile
#pragma unroll
    for (int u = 0; u < 2; u++) {
        int c = tid + u * 256;
        int row = c >> 3, off = (c & 7) << 3;
        float4 v0 = *(const float4*)(q + (size_t)(b * SEQ + i0 + row) * Hdim + h * DHEAD + off);
        float4 v1 = *(const float4*)(q + (size_t)(b * SEQ + i0 + row) * Hdim + h * DHEAD + off + 4);
        *(float4*)&Qs[row][off]     = v0;
        *(float4*)&Qs[row][off + 4] = v1;
    }
    __syncthreads();

    // Q fragments in registers
    unsigned aq[8][2][4];
#pragma unroll
    for (int ks = 0; ks < 8; ks++) {
        int kk = ks * 8;
#pragma unroll
        for (int mt = 0; mt < 2; mt++) {
            int mr = wm + mt * 16 + r;
            aq[ks][mt][0] = __float_as_uint(Qs[mr    ][kk + cq]);
            aq[ks][mt][1] = __float_as_uint(Qs[mr + 8][kk + cq]);
            aq[ks][mt][2] = __float_as_uint(Qs[mr    ][kk + cq + 4]);
            aq[ks][mt][3] = __float_as_uint(Qs[mr + 8][kk + cq + 4]);
        }
    }

    // prologue K tile 0
#pragma unroll
    for (int u = 0; u < 2; u++) {
        int c = tid + u * 256;
        int row = c >> 3, off = (c & 7) << 3;
        const float* src = k + (size_t)(b * SEQ + row) * Hdim + h * DHEAD + off;
        unsigned d = (unsigned)__cvta_generic_to_shared(&Ks[0][row][off]);
        CPA16(d, src); CPA16(d + 16, src + 4);
    }
    cp_commit();

    // ---- scores phase ----
    for (int jt = 0; jt < 8; jt++) {
        int cur = jt & 1;
        __syncthreads();
        if (jt + 1 < 8) {
            int j0 = (jt + 1) * 64;
#pragma unroll
            for (int u = 0; u < 2; u++) {
                int c = tid + u * 256;
                int row = c >> 3, off = (c & 7) << 3;
                const float* src = k + (size_t)(b * SEQ + j0 + row) * Hdim + h * DHEAD + off;
                unsigned d = (unsigned)__cvta_generic_to_shared(&Ks[cur ^ 1][row][off]);
                CPA16(d, src); CPA16(d + 16, src + 4);
            }
        }
        cp_commit();
        asm volatile("cp.async.wait_group 1;");
        __syncthreads();

        float acc[2][2][4];
#pragma unroll
        for (int i = 0; i < 2; i++)
#pragma unroll
            for (int j = 0; j < 2; j++)
#pragma unroll
                for (int t = 0; t < 4; t++) acc[i][j][t] = 0.f;

#pragma unroll
        for (int ks = 0; ks < 8; ks++) {
            int kk = ks * 8;
            unsigned bf[2][2];
#pragma unroll
            for (int nt = 0; nt < 2; nt++) {
                int nn = wn + nt * 8 + r;
                bf[nt][0] = __float_as_uint(Ks[cur][nn][kk + cq]);
                bf[nt][1] = __float_as_uint(Ks[cur][nn][kk + cq + 4]);
            }
#pragma unroll
            for (int mt = 0; mt < 2; mt++)
#pragma unroll
                for (int nt = 0; nt < 2; nt++)
                    mma8(acc[mt][nt], aq[ks][mt][0], aq[ks][mt][1],
                         aq[ks][mt][2], aq[ks][mt][3], bf[nt][0], bf[nt][1]);
        }

#pragma unroll
        for (int mt = 0; mt < 2; mt++) {
            int row = wm + mt * 16 + r;
#pragma unroll
            for (int nt = 0; nt < 2; nt++) {
                int jcol = jt * 64 + wn + nt * 8 + cq * 2;
                float2 ab = *(const float2*)&g_abias[b * SEQ + jcol];
                *(float2*)&S[row][jcol] =
                    make_float2(acc[mt][nt][0] * 0.125f + ab.x,
                                acc[mt][nt][1] * 0.125f + ab.y);
                *(float2*)&S[row + 8][jcol] =
                    make_float2(acc[mt][nt][2] * 0.125f + ab.x,
                                acc[mt][nt][3] * 0.125f + ab.y);
            }
        }
    }

    // prefetch V tile 0 (hidden under softmax)
#pragma unroll
    for (int u = 0; u < 2; u++) {
        int c = tid + u * 256;
        int row = c >> 3, off = (c & 7) << 3;
        const float* src = v + (size_t)(b * SEQ + row) * Hdim + h * DHEAD + off;
        unsigned d = (unsigned)__cvta_generic_to_shared(&Ks[0][row][off]);
        CPA16(d, src); CPA16(d + 16, src + 4);
    }
    cp_commit();
    __syncthreads();

    // ---- softmax (probabilities stay in smem, tf32-rounded) ----
#pragma unroll
    for (int rr = 0; rr < 8; rr++) {
        int row = warp * 8 + rr;
        float vals[16];
        float m = -1e30f;
#pragma unroll
        for (int t = 0; t < 16; t++) {
            vals[t] = S[row][lane + t * 32];
            m = fmaxf(m, vals[t]);
        }
#pragma unroll
        for (int off = 16; off; off >>= 1) m = fmaxf(m, __shfl_xor_sync(0xFFFFFFFFu, m, off));
        float s = 0.f;
#pragma unroll
        for (int t = 0; t < 16; t++) { vals[t] = expf(vals[t] - m); s += vals[t]; }
#pragma unroll
        for (int off = 16; off; off >>= 1) s += __shfl_xor_sync(0xFFFFFFFFu, s, off);
        float inv = 1.f / s;
#pragma unroll
        for (int t = 0; t < 16; t++)
            S[row][lane + t * 32] = roundtf(vals[t] * inv);
    }

    // ---- P@V phase: O(64x64) = S(64x512) @ V(512x64) ----
    int wmv = (warp >> 1) * 16;     // 4 m-warps
    int wnv = (warp & 1) * 32;      // 2 n-warps
    float acco[4][4];
#pragma unroll
    for (int j = 0; j < 4; j++)
#pragma unroll
        for (int t = 0; t < 4; t++) acco[j][t] = 0.f;

    for (int jt = 0; jt < 8; jt++) {
        int cur = jt & 1;
        __syncthreads();
        if (jt + 1 < 8) {
            int j0 = (jt + 1) * 64;
#pragma unroll
            for (int u = 0; u < 2; u++) {
                int c = tid + u * 256;
                int row = c >> 3, off = (c & 7) << 3;
                const float* src = v + (size_t)(b * SEQ + j0 + row) * Hdim + h * DHEAD + off;
                unsigned d = (unsigned)__cvta_generic_to_shared(&Ks[cur ^ 1][row][off]);
                CPA16(d, src); CPA16(d + 16, src + 4);
            }
        }
        cp_commit();
        asm volatile("cp.async.wait_group 1;");
        __syncthreads();

#pragma unroll
        for (int kg = 0; kg < 8; kg++) {
            int kk = kg * 8;
            int scol = jt * 64 + kk;
            unsigned a0 = __float_as_uint(S[wmv + r    ][scol + cq]);
            unsigned a1 = __float_as_uint(S[wmv + r + 8][scol + cq]);
            unsigned a2 = __float_as_uint(S[wmv + r    ][scol + cq + 4]);
            unsigned a3 = __float_as_uint(S[wmv + r + 8][scol + cq + 4]);
#pragma unroll
            for (int nt = 0; nt < 4; nt++) {
                int nn = wnv + nt * 8 + r;
                unsigned b0 = __float_as_uint(Ks[cur][kk + cq    ][nn]);
                unsigned b1 = __float_as_uint(Ks[cur][kk + cq + 4][nn]);
                mma8(acco[nt], a0, a1, a2, a3, b0, b1);
            }
        }
    }

    // epilogue: write ctx (tf32-rounded, feeds O-proj)
#pragma unroll
    for (int nt = 0; nt < 4; nt++) {
        int irow = b * SEQ + i0 + wmv + r;
        int col = h * DHEAD + wnv + nt * 8 + cq * 2;
        *(float2*)&ctx[(size_t)irow * Hdim + col] =
            make_float2(roundtf(acco[nt][0]), roundtf(acco[nt][1]));
        *(float2*)&ctx[(size_t)(irow + 8) * Hdim + col] =
            make_float2(roundtf(acco[nt][2]), roundtf(acco[nt][3]));
    }
}

// ---------------- heads: entity logits + pi/pj for relations ------------------
__global__ __launch_bounds__(256) void heads_kernel(
    const float* __restrict__ x, const float* __restrict__ W_ent,
    const float* __restrict__ b_ent, const float* __restrict__ W_rel,
    const float* __restrict__ b_rel, float* __restrict__ ent_out)
{
    int t = blockIdx.x;
    int tid = threadIdx.x;
    __shared__ float xs[Hdim];
    for (int i = tid; i < Hdim; i += 256) xs[i] = x[(size_t)t * Hdim + i];
    __syncthreads();
    int warp = tid >> 5, lane = tid & 31;
    for (int o = warp; o < NEnt + 2 * NRel; o += 8) {
        float s = 0.f;
        if (o < NEnt) {
            for (int k = lane; k < Hdim; k += 32) s += xs[k] * W_ent[(size_t)k * NEnt + o];
        } else if (o < NEnt + NRel) {
            int rr = o - NEnt;
            for (int k = lane; k < Hdim; k += 32) s += xs[k] * W_rel[(size_t)k * NRel + rr];
        } else {
            int rr = o - NEnt - NRel;
            for (int k = lane; k < Hdim; k += 32) s += xs[k] * W_rel[(size_t)(Hdim + k) * NRel + rr];
        }
#pragma unroll
        for (int off = 16; off; off >>= 1) s += __shfl_xor_sync(0xFFFFFFFFu, s, off);
        if (lane == 0) {
            if (o < NEnt)             ent_out[(size_t)t * NEnt + o] = s + b_ent[o];
            else if (o < NEnt + NRel) g_pi[t * NRel + (o - NEnt)] = s;
            else                      g_pj[t * NRel + (o - NEnt - NRel)] = s + b_rel[o - NEnt - NRel];
        }
    }
}

// ---------------- relation broadcast ------------------------------------------
__global__ __launch_bounds__(256) void relation_kernel(float* __restrict__ out)
{
    int bi = blockIdx.x;
    int b = bi >> 9;
    __shared__ float ps[NRel];
    if (threadIdx.x < NRel) ps[threadIdx.x] = g_pi[bi * NRel + threadIdx.x];
    __syncthreads();
    const float* pjb = g_pj + (size_t)(b << 9) * NRel;
    float* o = out + (size_t)bi * SEQ * NRel;
    for (int idx = threadIdx.x; idx < SEQ * NRel; idx += 256) {
        int r = idx % NRel;
        o[idx] = ps[r] + pjb[idx];
    }
}

// ---------------- host orchestration -----------------------------------------
extern "C" void kernel_launch(void* const* d_in, const int* in_sizes, int n_in,
                              void* d_out, int out_size)
{
    const int*   input_ids = (const int*)  d_in[0];
    const int*   attn_mask = (const int*)  d_in[1];
    const float* emb_word  = (const float*)d_in[2];
    const float* emb_pos   = (const float*)d_in[3];
    const float* emb_type  = (const float*)d_in[4];
    const float* emb_ln_g  = (const float*)d_in[5];
    const float* emb_ln_b  = (const float*)d_in[6];
    const float* Wq = (const float*)d_in[7];
    const float* bq = (const float*)d_in[8];
    const float* Wk = (const float*)d_in[9];
    const float* bk = (const float*)d_in[10];
    const float* Wv = (const float*)d_in[11];
    const float* bv = (const float*)d_in[12];
    const float* Wo = (const float*)d_in[13];
    const float* bo = (const float*)d_in[14];
    const float* ln1_g = (const float*)d_in[15];
    const float* ln1_b = (const float*)d_in[16];
    const float* W1 = (const float*)d_in[17];
    const float* b1 = (const float*)d_in[18];
    const float* W2 = (const float*)d_in[19];
    const float* b2 = (const float*)d_in[20];
    const float* ln2_g = (const float*)d_in[21];
    const float* ln2_b = (const float*)d_in[22];
    const float* W_ent = (const float*)d_in[23];
    const float* b_ent = (const float*)d_in[24];
    const float* W_rel = (const float*)d_in[25];
    const float* b_rel = (const float*)d_in[26];

    float *x, *xr, *q, *k, *v, *ctx, *ffn;
    cudaGetSymbolAddress((void**)&x,   g_x);
    cudaGetSymbolAddress((void**)&xr,  g_xr);
    cudaGetSymbolAddress((void**)&q,   g_q);
    cudaGetSymbolAddress((void**)&k,   g_k);
    cudaGetSymbolAddress((void**)&v,   g_v);
    cudaGetSymbolAddress((void**)&ctx, g_ctx);
    cudaGetSymbolAddress((void**)&ffn, g_ffn);

    cudaFuncSetAttribute(attn_fused_kernel,
                         cudaFuncAttributeMaxDynamicSharedMemorySize, ATTN_SMEM);
    cudaFuncSetAttribute(tf32_gemm_kernel,
                         cudaFuncAttributeMaxDynamicSharedMemorySize, GEMM_SMEM);
    cudaFuncSetAttribute(tf32_gemm64_kernel,
                         cudaFuncAttributeMaxDynamicSharedMemorySize, G64_SMEM);

    embed_ln_kernel<<<MTOK, 256>>>(input_ids, emb_word, emb_pos, emb_type,
                                   emb_ln_g, emb_ln_b);
    abias_kernel<<<(BATCH * SEQ + 255) / 256, 256>>>(attn_mask);

    dim3 gQKV(Hdim / 128, MTOK / 128, 3);
    dim3 gF1(FFdim / 128, MTOK / 128, 1);
    dim3 g64(Hdim / 128, MTOK / 64);          // 6 x 32 = 192 blocks
    dim3 gA(SEQ / 64, BATCH * NHEADS);        // 8 x 48 = 384 blocks

    for (int l = 0; l < NLAY; l++) {
        size_t wHH = (size_t)l * Hdim * Hdim;
        size_t wH  = (size_t)l * Hdim;
        size_t wHF = (size_t)l * Hdim * FFdim;
        tf32_gemm_kernel<<<gQKV, 256, GEMM_SMEM>>>(xr, Wq + wHH, Wk + wHH, Wv + wHH,
                                        bq + wH, bk + wH, bv + wH,
                                        q, k, v, MTOK, Hdim, Hdim, 0, 1);
        attn_fused_kernel<<<gA, 256, ATTN_SMEM>>>(q, k, v, ctx);
        tf32_gemm64_kernel<<<g64, 256, G64_SMEM>>>(ctx, Wo + wHH, bo + wH,
                                                   q, MTOK, Hdim, Hdim, 0, 0);
        add_ln_kernel<<<MTOK, 256>>>(x, q, ln1_g + wH, ln1_b + wH);
        tf32_gemm_kernel<<<gF1, 256, GEMM_SMEM>>>(xr, W1 + wHF, W1 + wHF, W1 + wHF,
                                       b1 + (size_t)l * FFdim, b1 + (size_t)l * FFdim, b1 + (size_t)l * FFdim,
                                       ffn, ffn, ffn, MTOK, FFdim, Hdim, 1, 1);
        tf32_gemm64_kernel<<<g64, 256, G64_SMEM>>>(ffn, W2 + wHF, b2 + wH,
                                                   q, MTOK, Hdim, FFdim, 0, 0);
        add_ln_kernel<<<MTOK, 256>>>(x, q, ln2_g + wH, ln2_b + wH);
    }

    float* out = (float*)d_out;
    heads_kernel<<<MTOK, 256>>>(x, W_ent, b_ent, W_rel, b_rel, out);
    relation_kernel<<<MTOK, 256>>>(out + (size_t)MTOK * NEnt);
}